// round 17
// baseline (speedup 1.0000x reference)
#include <cuda_runtime.h>
#include <cuda_bf16.h>
#include <math.h>
#include <stdint.h>
typedef __nv_bfloat16 bf16;

#define BBATCH 8
#define SSEQ 512
#define TSEQ 256
#define DMOD 512
#define HHEADS 8
#define DFFN 2048
#define LLAY 6
#define VTOK 32000
#define MS (BBATCH*SSEQ)
#define MT (BBATCH*TSEQ)

#define W512 (512ull*512ull)
#define WFF  (512ull*2048ull)
constexpr size_t O_EQKV = 0;
constexpr size_t O_EWO  = O_EQKV + 18ull*W512;
constexpr size_t O_EW1  = O_EWO  + 6ull*W512;
constexpr size_t O_EW2  = O_EW1  + 6ull*WFF;
constexpr size_t O_DSQKV= O_EW2  + 6ull*WFF;
constexpr size_t O_DSO  = O_DSQKV+ 18ull*W512;
constexpr size_t O_DCQ  = O_DSO  + 6ull*W512;
constexpr size_t O_DCKV = O_DCQ  + 6ull*W512;
constexpr size_t O_DCO  = O_DCKV + 12ull*W512;
constexpr size_t O_DW1  = O_DCO  + 6ull*W512;
constexpr size_t O_DW2  = O_DW1  + 6ull*WFF;
constexpr size_t O_EMB  = O_DW2  + 6ull*WFF;
constexpr size_t W_TOTAL= O_EMB + (size_t)VTOK*DMOD;

__device__ bf16  g_whi[W_TOTAL];
__device__ bf16  g_wlo[W_TOTAL];
__device__ float g_x[MS*DMOD];
__device__ float g_y[MT*DMOD];
__device__ bf16  g_qkvh[MS*1536], g_qkvl[MS*1536];
__device__ bf16  g_cqh[MT*DMOD],  g_cql[MT*DMOD];
__device__ bf16  g_ckvh[MS*1024], g_ckvl[MS*1024];
__device__ bf16  g_hh[MS*DMOD],  g_hl[MS*DMOD];
__device__ bf16  g_ath[MS*DMOD], g_atl[MS*DMOD];
__device__ bf16  g_fh[MS*DFFN],  g_fl[MS*DFFN];
__device__ bf16  g_xh[MS*DMOD],  g_xl[MS*DMOD];

#define SWZ(o)   ((o) ^ (((o) >> 3) & 0x70))
#define SWZ64(o) ((o) ^ (((o) >> 3) & 0x30))
__device__ __forceinline__ uint32_t s2u(const void* p){
    uint32_t a; asm("{ .reg .u64 t; cvta.to.shared.u64 t, %1; cvt.u32.u64 %0, t; }" : "=r"(a) : "l"(p)); return a;
}
__device__ __forceinline__ void cpa16(uint32_t dst, const void* src){
    asm volatile("cp.async.cg.shared.global [%0], [%1], 16;" :: "r"(dst), "l"(src));
}
#define CP_COMMIT() asm volatile("cp.async.commit_group;" ::: "memory")
#define CP_WAIT1()  asm volatile("cp.async.wait_group 1;" ::: "memory")
#define CP_WAIT0()  asm volatile("cp.async.wait_group 0;" ::: "memory")
__device__ __forceinline__ void ldm4(uint32_t& r0, uint32_t& r1, uint32_t& r2, uint32_t& r3, uint32_t a){
    asm volatile("ldmatrix.sync.aligned.m8n8.x4.shared.b16 {%0,%1,%2,%3}, [%4];"
        : "=r"(r0), "=r"(r1), "=r"(r2), "=r"(r3) : "r"(a));
}
__device__ __forceinline__ void ldm4t(uint32_t& r0, uint32_t& r1, uint32_t& r2, uint32_t& r3, uint32_t a){
    asm volatile("ldmatrix.sync.aligned.m8n8.x4.trans.shared.b16 {%0,%1,%2,%3}, [%4];"
        : "=r"(r0), "=r"(r1), "=r"(r2), "=r"(r3) : "r"(a));
}
__device__ __forceinline__ void mma16816(float* c, const uint32_t* a, uint32_t b0, uint32_t b1){
    asm volatile("mma.sync.aligned.m16n8k16.row.col.f32.bf16.bf16.f32 "
        "{%0,%1,%2,%3}, {%4,%5,%6,%7}, {%8,%9}, {%0,%1,%2,%3};"
        : "+f"(c[0]), "+f"(c[1]), "+f"(c[2]), "+f"(c[3])
        : "r"(a[0]), "r"(a[1]), "r"(a[2]), "r"(a[3]), "r"(b0), "r"(b1));
}
__device__ __forceinline__ void split2(float v, bf16* ph, bf16* pl){
    bf16 h = __float2bfloat16_rn(v);
    *ph = h; *pl = __float2bfloat16_rn(v - __bfloat162float(h));
}
__device__ __forceinline__ void split_pack(float s0, float s1, uint32_t& ph, uint32_t& pl){
    bf16 h0 = __float2bfloat16_rn(s0), h1 = __float2bfloat16_rn(s1);
    bf16 l0 = __float2bfloat16_rn(s0 - __bfloat162float(h0));
    bf16 l1 = __float2bfloat16_rn(s1 - __bfloat162float(h1));
    ph = (uint32_t)__bfloat16_as_ushort(h0) | ((uint32_t)__bfloat16_as_ushort(h1) << 16);
    pl = (uint32_t)__bfloat16_as_ushort(l0) | ((uint32_t)__bfloat16_as_ushort(l1) << 16);
}
__device__ __forceinline__ void sst32(uint32_t a, uint32_t v){ asm volatile("st.shared.u32 [%0], %1;" :: "r"(a), "r"(v) : "memory"); }
__device__ __forceinline__ uint32_t sld32(uint32_t a){ uint32_t v; asm volatile("ld.shared.u32 %0, [%1];" : "=r"(v) : "r"(a)); return v; }
__device__ __forceinline__ void sstf(uint32_t a, float v){ asm volatile("st.shared.f32 [%0], %1;" :: "r"(a), "f"(v) : "memory"); }
__device__ __forceinline__ float sldf(uint32_t a){ float v; asm volatile("ld.shared.f32 %0, [%1];" : "=f"(v) : "r"(a)); return v; }
__device__ __forceinline__ int rbbucket(int n){
    int sign = (n < 0) ? 1 : 0; int na = (n < 0) ? -n : n;
    return ((na < 16) ? na : 15) + sign * 16;
}

// ---------------- HMMA GEMM v5: 128 thr / 4 warps (2x2), block 128x128, warp tile 64x64,
// BK=32, SW64, 3 stages x 32KB = 96KB, 2 CTAs/SM. LDSM bytes/MMA halved vs v4.
// EPI: 0 f32 | 1 f32+res | 2 pair+bias+relu | 3 f32+bias+res | 4 pair
template<int EPI>
__global__ __launch_bounds__(128, 2) void bgemm(
    const bf16* __restrict__ Ah, const bf16* __restrict__ Al,
    const bf16* __restrict__ Bh, const bf16* __restrict__ Bl,
    const float* __restrict__ bias, const float* __restrict__ res,
    float* __restrict__ C, bf16* __restrict__ Ch, bf16* __restrict__ Cl,
    int M, int N, int K)
{
    extern __shared__ char dsm[];   // 3 stages x (Ah 8K | Al 8K | Bh 8K | Bl 8K) = 96KB
    const int tid = threadIdx.x, wid = tid >> 5, lane = tid & 31;
    const int bm = blockIdx.y * 128, bn = blockIdx.x * 128;
    const int mbase = (wid >> 1) * 64, nbase = (wid & 1) * 64;
    const uint32_t sb0 = s2u(dsm);
    const int arow = (lane & 7) + ((lane >> 3) & 1) * 8, acolb = ((lane >> 4) & 1) * 16;
    const int brow = (lane & 7) + ((lane >> 4) & 1) * 8, bcolb = ((lane >> 3) & 1) * 16;

    float acc[4][8][4];
    #pragma unroll
    for (int a = 0; a < 4; a++)
        #pragma unroll
        for (int b = 0; b < 8; b++)
            #pragma unroll
            for (int c = 0; c < 4; c++) acc[a][b][c] = 0.f;

    const int nt = K >> 5;
    auto issue = [&](int i) {
        uint32_t sb = sb0 + (i % 3) * 32768;
        const int k0 = i << 5;
        #pragma unroll
        for (int it = 0; it < 16; it++) {
            int idx = tid + it * 128;
            int mat = idx >> 9, v = idx & 511, r = v >> 2, c16 = v & 3;
            const bf16* g;
            if      (mat == 0) g = Ah + (size_t)(bm + r) * K + k0 + c16 * 8;
            else if (mat == 1) g = Al + (size_t)(bm + r) * K + k0 + c16 * 8;
            else if (mat == 2) g = Bh + (size_t)(bn + r) * K + k0 + c16 * 8;
            else               g = Bl + (size_t)(bn + r) * K + k0 + c16 * 8;
            cpa16(sb + mat * 8192 + SWZ64(r * 64 + c16 * 16), g);
        }
        CP_COMMIT();
    };

    issue(0); issue(1);
    for (int i = 0; i < nt; i++) {
        if (i == nt - 1) { CP_WAIT0(); } else { CP_WAIT1(); }
        __syncthreads();
        if (i + 2 < nt) issue(i + 2);
        const uint32_t base = sb0 + (i % 3) * 32768;

        #pragma unroll
        for (int ks = 0; ks < 2; ks++) {
            uint32_t ah[4][4], al[4][4], bh[8][2], bl[8][2];
            #pragma unroll
            for (int mf = 0; mf < 4; mf++) {
                uint32_t off = SWZ64((mbase + mf * 16 + arow) * 64 + ks * 32 + acolb);
                ldm4(ah[mf][0], ah[mf][1], ah[mf][2], ah[mf][3], base + off);
                ldm4(al[mf][0], al[mf][1], al[mf][2], al[mf][3], base + 8192 + off);
            }
            #pragma unroll
            for (int p = 0; p < 4; p++) {
                uint32_t off = SWZ64((nbase + p * 16 + brow) * 64 + ks * 32 + bcolb);
                ldm4(bh[2*p][0], bh[2*p][1], bh[2*p+1][0], bh[2*p+1][1], base + 16384 + off);
                ldm4(bl[2*p][0], bl[2*p][1], bl[2*p+1][0], bl[2*p+1][1], base + 24576 + off);
            }
            #pragma unroll
            for (int pass = 0; pass < 3; pass++) {
                #pragma unroll
                for (int mf = 0; mf < 4; mf++)
                    #pragma unroll
                    for (int nf = 0; nf < 8; nf++) {
                        const uint32_t* a = (pass == 2) ? al[mf] : ah[mf];
                        const uint32_t* b = (pass == 1) ? bl[nf] : bh[nf];
                        mma16816(acc[mf][nf], a, b[0], b[1]);
                    }
            }
        }
    }

    #pragma unroll
    for (int mf = 0; mf < 4; mf++) {
        int m0 = bm + mbase + mf * 16 + (lane >> 2);
        #pragma unroll
        for (int nf = 0; nf < 8; nf++) {
            int n = bn + nbase + nf * 8 + (lane & 3) * 2;
            float* a = acc[mf][nf];
            #pragma unroll
            for (int hr = 0; hr < 2; hr++) {
                int m = m0 + hr * 8;
                float o0 = a[hr * 2 + 0], o1 = a[hr * 2 + 1];
                if (EPI == 2 || EPI == 3) { o0 += bias[n]; o1 += bias[n + 1]; }
                if (EPI == 2) { o0 = fmaxf(o0, 0.f); o1 = fmaxf(o1, 0.f); }
                if (EPI == 1 || EPI == 3) {
                    const float* rr = res + (size_t)m * N + n;
                    o0 += rr[0]; o1 += rr[1];
                }
                if (EPI == 2 || EPI == 4) {
                    size_t o = (size_t)m * N + n;
                    split2(o0, Ch + o, Cl + o);
                    split2(o1, Ch + o + 1, Cl + o + 1);
                } else {
                    *(float2*)(C + (size_t)m * N + n) = make_float2(o0, o1);
                }
            }
        }
    }
}

// ---------------- HMMA flash attention: 64 queries/block, 256 threads ----------------
#define ASMEM 180480
__global__ __launch_bounds__(256, 1) void attn_mma(
    const bf16* __restrict__ Qh_g, const bf16* __restrict__ Ql_g, int qstr,
    const bf16* __restrict__ Kh_g, const bf16* __restrict__ Kl_g,
    const bf16* __restrict__ Vh_g, const bf16* __restrict__ Vl_g, int kvstr,
    const int* __restrict__ key_ids, const float* __restrict__ remb,
    bf16* __restrict__ Oh, bf16* __restrict__ Ol,
    int qlen, int klen, int causal)
{
    extern __shared__ char sm[];
    const int tid = threadIdx.x, wid = tid >> 5, lane = tid & 31;
    const int b = blockIdx.z, h = blockIdx.y, i0 = blockIdx.x * 64;
    const uint32_t sb = s2u(sm);
    const uint32_t PH = sb, PL = sb + 65536, KVH = sb + 131072, KVL = sb + 147456;
    const uint32_t QHs = sb + 163840, QLs = sb + 172032, INV = sb + 180224;
    const int wm = wid >> 2, wn = wid & 3;
    const int arow = (lane & 7) + ((lane >> 3) & 1) * 8, acolb = ((lane >> 4) & 1) * 16;
    const int brow = (lane & 7) + ((lane >> 4) & 1) * 8, bcolb = ((lane >> 3) & 1) * 16;

    for (int idx = tid; idx < 512; idx += 256) {
        int r = idx >> 3, c = (idx & 7) << 4;
        size_t go = (size_t)(b * qlen + i0 + r) * qstr + h * 64 + (c >> 1);
        cpa16(QHs + SWZ(r * 128 + c), Qh_g + go);
        cpa16(QLs + SWZ(r * 128 + c), Ql_g + go);
    }
    CP_COMMIT();
    const int nch = klen >> 7;

    for (int kc = 0; kc < nch; kc++) {
        for (int idx = tid; idx < 1024; idx += 256) {
            int r = idx >> 3, c = (idx & 7) << 4;
            size_t go = (size_t)(b * klen + kc * 128 + r) * kvstr + h * 64 + (c >> 1);
            cpa16(KVH + SWZ(r * 128 + c), Kh_g + go);
            cpa16(KVL + SWZ(r * 128 + c), Kl_g + go);
        }
        CP_COMMIT(); CP_WAIT0(); __syncthreads();
        float sacc[2][4][4];
        #pragma unroll
        for (int a = 0; a < 2; a++)
            #pragma unroll
            for (int bq = 0; bq < 4; bq++)
                #pragma unroll
                for (int c = 0; c < 4; c++) sacc[a][bq][c] = 0.f;
        #pragma unroll
        for (int ks = 0; ks < 4; ks++) {
            uint32_t qa[2][4], ql[2][4], kb[4][2], kl[4][2];
            #pragma unroll
            for (int mf = 0; mf < 2; mf++) {
                uint32_t off = SWZ((wm * 32 + mf * 16 + arow) * 128 + ks * 32 + acolb);
                ldm4(qa[mf][0], qa[mf][1], qa[mf][2], qa[mf][3], QHs + off);
                ldm4(ql[mf][0], ql[mf][1], ql[mf][2], ql[mf][3], QLs + off);
            }
            #pragma unroll
            for (int p = 0; p < 2; p++) {
                uint32_t off = SWZ((wn * 32 + p * 16 + brow) * 128 + ks * 32 + bcolb);
                ldm4(kb[2*p][0], kb[2*p][1], kb[2*p+1][0], kb[2*p+1][1], KVH + off);
                ldm4(kl[2*p][0], kl[2*p][1], kl[2*p+1][0], kl[2*p+1][1], KVL + off);
            }
            #pragma unroll
            for (int pass = 0; pass < 3; pass++) {
                #pragma unroll
                for (int mf = 0; mf < 2; mf++)
                    #pragma unroll
                    for (int nf = 0; nf < 4; nf++) {
                        const uint32_t* a = (pass == 2) ? ql[mf] : qa[mf];
                        const uint32_t* bb = (pass == 1) ? kl[nf] : kb[nf];
                        mma16816(sacc[mf][nf], a, bb[0], bb[1]);
                    }
            }
        }
        #pragma unroll
        for (int nf = 0; nf < 4; nf++) {
            int gk = kc * 128 + wn * 32 + nf * 8 + (lane & 3) * 2;
            int ki0 = key_ids[b * klen + gk], ki1 = key_ids[b * klen + gk + 1];
            #pragma unroll
            for (int mf = 0; mf < 2; mf++)
                #pragma unroll
                for (int hr = 0; hr < 2; hr++) {
                    int q = wm * 32 + mf * 16 + (lane >> 2) + hr * 8;
                    float s0 = sacc[mf][nf][hr*2] * 0.125f, s1 = sacc[mf][nf][hr*2+1] * 0.125f;
                    if (remb) {
                        s0 += remb[rbbucket(i0 + q - gk) * HHEADS + h];
                        s1 += remb[rbbucket(i0 + q - gk - 1) * HHEADS + h];
                    }
                    if (ki0 == 0 || (causal && gk     > i0 + q)) s0 = -1e30f;
                    if (ki1 == 0 || (causal && gk + 1 > i0 + q)) s1 = -1e30f;
                    uint32_t ph, pl; split_pack(s0, s1, ph, pl);
                    uint32_t off = (uint32_t)q * 1024 + (((uint32_t)gk * 2) ^ ((q & 7) << 4));
                    sst32(PH + off, ph); sst32(PL + off, pl);
                }
        }
        __syncthreads();
    }

    {
        int ni = klen >> 6;
        #pragma unroll
        for (int r = 0; r < 8; r++) {
            int q = wid * 8 + r;
            float m = -INFINITY;
            for (int it = 0; it < ni; it++) {
                uint32_t off = (uint32_t)q * 1024 + ((((uint32_t)(lane + it * 32)) * 4) ^ ((q & 7) << 4));
                uint32_t wh = sld32(PH + off), wl = sld32(PL + off);
                float a0 = __uint_as_float(wh << 16) + __uint_as_float(wl << 16);
                float a1 = __uint_as_float(wh & 0xffff0000u) + __uint_as_float(wl & 0xffff0000u);
                m = fmaxf(m, fmaxf(a0, a1));
            }
            #pragma unroll
            for (int o = 16; o; o >>= 1) m = fmaxf(m, __shfl_xor_sync(0xffffffffu, m, o));
            float sum = 0.f;
            for (int it = 0; it < ni; it++) {
                uint32_t off = (uint32_t)q * 1024 + ((((uint32_t)(lane + it * 32)) * 4) ^ ((q & 7) << 4));
                uint32_t wh = sld32(PH + off), wl = sld32(PL + off);
                float a0 = __uint_as_float(wh << 16) + __uint_as_float(wl << 16);
                float a1 = __uint_as_float(wh & 0xffff0000u) + __uint_as_float(wl & 0xffff0000u);
                float e0 = expf(a0 - m), e1 = expf(a1 - m);
                sum += e0 + e1;
                uint32_t ph, pl; split_pack(e0, e1, ph, pl);
                sst32(PH + off, ph); sst32(PL + off, pl);
            }
            #pragma unroll
            for (int o = 16; o; o >>= 1) sum += __shfl_xor_sync(0xffffffffu, sum, o);
            if (lane == 0) sstf(INV + q * 4, 1.0f / sum);
        }
    }
    __syncthreads();

    float oacc[2][2][4];
    #pragma unroll
    for (int a = 0; a < 2; a++)
        #pragma unroll
        for (int bq = 0; bq < 2; bq++)
            #pragma unroll
            for (int c = 0; c < 4; c++) oacc[a][bq][c] = 0.f;
    for (int kc = 0; kc < nch; kc++) {
        for (int idx = tid; idx < 1024; idx += 256) {
            int r = idx >> 3, c = (idx & 7) << 4;
            size_t go = (size_t)(b * klen + kc * 128 + r) * kvstr + h * 64 + (c >> 1);
            cpa16(KVH + SWZ(r * 128 + c), Vh_g + go);
            cpa16(KVL + SWZ(r * 128 + c), Vl_g + go);
        }
        CP_COMMIT(); CP_WAIT0(); __syncthreads();
        #pragma unroll
        for (int kk = 0; kk < 8; kk++) {
            uint32_t pa[2][4], pl2[2][4], vb[2][2], vl2[2][2];
            #pragma unroll
            for (int mf = 0; mf < 2; mf++) {
                int q = wm * 32 + mf * 16 + arow;
                uint32_t kb2 = (uint32_t)((kc * 128 + kk * 16) * 2) + acolb;
                uint32_t off = (uint32_t)q * 1024 + (kb2 ^ ((q & 7) << 4));
                ldm4(pa[mf][0], pa[mf][1], pa[mf][2], pa[mf][3], PH + off);
                ldm4(pl2[mf][0], pl2[mf][1], pl2[mf][2], pl2[mf][3], PL + off);
            }
            {
                int vr = kk * 16 + (lane & 7) + ((lane >> 3) & 1) * 8;
                int vc = wn * 32 + ((lane >> 4) & 1) * 16;
                ldm4t(vb[0][0], vb[0][1], vb[1][0], vb[1][1], KVH + SWZ(vr * 128 + vc));
                ldm4t(vl2[0][0], vl2[0][1], vl2[1][0], vl2[1][1], KVL + SWZ(vr * 128 + vc));
            }
            #pragma unroll
            for (int pass = 0; pass < 3; pass++) {
                #pragma unroll
                for (int mf = 0; mf < 2; mf++)
                    #pragma unroll
                    for (int nf = 0; nf < 2; nf++) {
                        const uint32_t* a = (pass == 2) ? pl2[mf] : pa[mf];
                        const uint32_t* v = (pass == 1) ? vl2[nf] : vb[nf];
                        mma16816(oacc[mf][nf], a, v[0], v[1]);
                    }
            }
        }
        __syncthreads();
    }
    #pragma unroll
    for (int mf = 0; mf < 2; mf++)
        #pragma unroll
        for (int hr = 0; hr < 2; hr++) {
            int q = wm * 32 + mf * 16 + (lane >> 2) + hr * 8;
            float inv = sldf(INV + q * 4);
            #pragma unroll
            for (int nf = 0; nf < 2; nf++) {
                int d = wn * 16 + nf * 8 + (lane & 3) * 2;
                size_t o = (size_t)(b * qlen + i0 + q) * DMOD + h * 64 + d;
                split2(oacc[mf][nf][hr*2]   * inv, Oh + o,     Ol + o);
                split2(oacc[mf][nf][hr*2+1] * inv, Oh + o + 1, Ol + o + 1);
            }
        }
}

// ---------------- weight prep ----------------
__global__ void wconv512_all(
    const float* p0, const float* p1, const float* p2, const float* p3,
    const float* p4, const float* p5, const float* p6, const float* p7,
    const float* p8, const float* p9, const float* p10, const float* p11,
    bf16* __restrict__ dh, bf16* __restrict__ dl)
{
    __shared__ float t[32][33];
    int z = blockIdx.z, mat = z / 6, l = z % 6;
    const float* s; size_t off;
    switch (mat) {
        case 0:  s = p0;  off = O_EQKV + (size_t)l*3*W512;          break;
        case 1:  s = p1;  off = O_EQKV + (size_t)l*3*W512 + W512;   break;
        case 2:  s = p2;  off = O_EQKV + (size_t)l*3*W512 + 2*W512; break;
        case 3:  s = p3;  off = O_EWO  + (size_t)l*W512;            break;
        case 4:  s = p4;  off = O_DSQKV + (size_t)l*3*W512;         break;
        case 5:  s = p5;  off = O_DSQKV + (size_t)l*3*W512 + W512;  break;
        case 6:  s = p6;  off = O_DSQKV + (size_t)l*3*W512 + 2*W512;break;
        case 7:  s = p7;  off = O_DSO  + (size_t)l*W512;            break;
        case 8:  s = p8;  off = O_DCQ  + (size_t)l*W512;            break;
        case 9:  s = p9;  off = O_DCKV + (size_t)l*2*W512;          break;
        case 10: s = p10; off = O_DCKV + (size_t)l*2*W512 + W512;   break;
        default: s = p11; off = O_DCO  + (size_t)l*W512;            break;
    }
    s += (size_t)l * 512 * 512;
    int n0 = blockIdx.x * 32, k0 = blockIdx.y * 32;
    int tx = threadIdx.x, ty = threadIdx.y;
    for (int r = 0; r < 32; r += 8)
        t[ty + r][tx] = s[(size_t)(k0 + ty + r) * 512 + n0 + tx];
    __syncthreads();
    bf16* oh = dh + off; bf16* ol = dl + off;
    for (int r = 0; r < 32; r += 8) {
        int n = n0 + ty + r, k = k0 + tx;
        split2(t[tx][ty + r], oh + (size_t)n * 512 + k, ol + (size_t)n * 512 + k);
    }
}
__global__ void wconvFF_all(
    const float* e1, const float* e2, const float* d1, const float* d2,
    bf16* __restrict__ dh, bf16* __restrict__ dl)
{
    __shared__ float t[32][33];
    int z = blockIdx.z, mat = z / 6, l = z % 6;
    const float* s; size_t off; int K, N;
    switch (mat) {
        case 0:  s = e1; off = O_EW1 + (size_t)l*WFF; K = 512;  N = 2048; break;
        case 1:  s = e2; off = O_EW2 + (size_t)l*WFF; K = 2048; N = 512;  break;
        case 2:  s = d1; off = O_DW1 + (size_t)l*WFF; K = 512;  N = 2048; break;
        default: s = d2; off = O_DW2 + (size_t)l*WFF; K = 2048; N = 512;  break;
    }
    s += (size_t)l * K * N;
    int ntn = N >> 5;
    int n0 = (blockIdx.x % ntn) * 32, k0 = (blockIdx.x / ntn) * 32;
    int tx = threadIdx.x, ty = threadIdx.y;
    for (int r = 0; r < 32; r += 8)
        t[ty + r][tx] = s[(size_t)(k0 + ty + r) * N + n0 + tx];
    __syncthreads();
    bf16* oh = dh + off; bf16* ol = dl + off;
    for (int r = 0; r < 32; r += 8) {
        int n = n0 + ty + r, k = k0 + tx;
        split2(t[tx][ty + r], oh + (size_t)n * K + k, ol + (size_t)n * K + k);
    }
}
__global__ void econv_kernel(const float* __restrict__ src, bf16* __restrict__ dh, bf16* __restrict__ dl, int n)
{
    int i = blockIdx.x * blockDim.x + threadIdx.x;
    if (i < n) split2(src[i], dh + i, dl + i);
}
__global__ void embed_kernel(const int* __restrict__ ids, const float* __restrict__ emb,
                             float* __restrict__ out, int ntok)
{
    int idx = blockIdx.x * blockDim.x + threadIdx.x;
    if (idx >= ntok * DMOD) return;
    int tok = idx >> 9, d = idx & 511;
    out[idx] = emb[(size_t)ids[tok] * DMOD + d] * 22.62741699796952f;
}
__global__ __launch_bounds__(256) void rmsnorm_pair_kernel(
    const float* __restrict__ x, const float* __restrict__ w,
    bf16* __restrict__ oh, bf16* __restrict__ ol)
{
    __shared__ float red[256];
    int row = blockIdx.x, t = threadIdx.x;
    const float* xr = x + (size_t)row * DMOD;
    float a0 = xr[t], a1 = xr[t + 256];
    red[t] = a0 * a0 + a1 * a1;
    __syncthreads();
    for (int st = 128; st > 0; st >>= 1) { if (t < st) red[t] += red[t + st]; __syncthreads(); }
    float scale = 1.0f / sqrtf(red[0] * (1.0f / 512.0f) + 1e-8f);
    size_t o = (size_t)row * DMOD;
    split2(a0 * scale * w[t],       oh + o + t,       ol + o + t);
    split2(a1 * scale * w[t + 256], oh + o + t + 256, ol + o + t + 256);
}

#define DSMB 98304

extern "C" void kernel_launch(void* const* d_in, const int* in_sizes, int n_in,
                              void* d_out, int out_size)
{
    const int*   src_ids = (const int*)  d_in[0];
    const int*   tgt_ids = (const int*)  d_in[1];
    const float* src_emb = (const float*)d_in[2];
    const float* tgt_emb = (const float*)d_in[3];
    const float* rel_enc = (const float*)d_in[4];
    const float* rel_dec = (const float*)d_in[5];
    const float* enc_n1  = (const float*)d_in[6];
    const float* enc_n2  = (const float*)d_in[7];
    const float* enc_Wq  = (const float*)d_in[8];
    const float* enc_Wk  = (const float*)d_in[9];
    const float* enc_Wv  = (const float*)d_in[10];
    const float* enc_Wo  = (const float*)d_in[11];
    const float* enc_W1  = (const float*)d_in[12];
    const float* enc_b1  = (const float*)d_in[13];
    const float* enc_W2  = (const float*)d_in[14];
    const float* enc_b2  = (const float*)d_in[15];
    const float* dec_n1  = (const float*)d_in[16];
    const float* dec_n2  = (const float*)d_in[17];
    const float* dec_n3  = (const float*)d_in[18];
    const float* dec_sWq = (const float*)d_in[19];
    const float* dec_sWk = (const float*)d_in[20];
    const float* dec_sWv = (const float*)d_in[21];
    const float* dec_sWo = (const float*)d_in[22];
    const float* dec_cWq = (const float*)d_in[23];
    const float* dec_cWk = (const float*)d_in[24];
    const float* dec_cWv = (const float*)d_in[25];
    const float* dec_cWo = (const float*)d_in[26];
    const float* dec_W1  = (const float*)d_in[27];
    const float* dec_b1  = (const float*)d_in[28];
    const float* dec_W2  = (const float*)d_in[29];
    const float* dec_b2  = (const float*)d_in[30];
    const float* final_w = (const float*)d_in[31];
    float* out = (float*)d_out;

    bf16 *whi, *wlo, *hh, *hl, *ath, *atl, *fh, *fl, *xh, *xl;
    bf16 *qkvh, *qkvl, *cqh, *cql, *ckvh, *ckvl;
    float *x, *y;
    cudaGetSymbolAddress((void**)&whi, g_whi); cudaGetSymbolAddress((void**)&wlo, g_wlo);
    cudaGetSymbolAddress((void**)&x, g_x);     cudaGetSymbolAddress((void**)&y, g_y);
    cudaGetSymbolAddress((void**)&qkvh, g_qkvh); cudaGetSymbolAddress((void**)&qkvl, g_qkvl);
    cudaGetSymbolAddress((void**)&cqh, g_cqh);   cudaGetSymbolAddress((void**)&cql, g_cql);
    cudaGetSymbolAddress((void**)&ckvh, g_ckvh); cudaGetSymbolAddress((void**)&ckvl, g_ckvl);
    cudaGetSymbolAddress((void**)&hh, g_hh);   cudaGetSymbolAddress((void**)&hl, g_hl);
    cudaGetSymbolAddress((void**)&ath, g_ath); cudaGetSymbolAddress((void**)&atl, g_atl);
    cudaGetSymbolAddress((void**)&fh, g_fh);   cudaGetSymbolAddress((void**)&fl, g_fl);
    cudaGetSymbolAddress((void**)&xh, g_xh);   cudaGetSymbolAddress((void**)&xl, g_xl);

    cudaFuncSetAttribute(bgemm<0>, cudaFuncAttributeMaxDynamicSharedMemorySize, DSMB);
    cudaFuncSetAttribute(bgemm<1>, cudaFuncAttributeMaxDynamicSharedMemorySize, DSMB);
    cudaFuncSetAttribute(bgemm<2>, cudaFuncAttributeMaxDynamicSharedMemorySize, DSMB);
    cudaFuncSetAttribute(bgemm<3>, cudaFuncAttributeMaxDynamicSharedMemorySize, DSMB);
    cudaFuncSetAttribute(bgemm<4>, cudaFuncAttributeMaxDynamicSharedMemorySize, DSMB);
    cudaFuncSetAttribute(attn_mma, cudaFuncAttributeMaxDynamicSharedMemorySize, ASMEM);

    auto G1 = [&](const bf16* ah, const bf16* al, size_t off, const float* res, float* C, int M, int N, int K) {
        bgemm<1><<<dim3(N/128, M/128), 128, DSMB>>>(ah, al, whi+off, wlo+off, nullptr, res, C, nullptr, nullptr, M, N, K);
    };
    auto G2 = [&](const bf16* ah, const bf16* al, size_t off, const float* bias, bf16* ch, bf16* cl, int M, int N, int K) {
        bgemm<2><<<dim3(N/128, M/128), 128, DSMB>>>(ah, al, whi+off, wlo+off, bias, nullptr, nullptr, ch, cl, M, N, K);
    };
    auto G3 = [&](const bf16* ah, const bf16* al, size_t off, const float* bias, const float* res, float* C, int M, int N, int K) {
        bgemm<3><<<dim3(N/128, M/128), 128, DSMB>>>(ah, al, whi+off, wlo+off, bias, res, C, nullptr, nullptr, M, N, K);
    };
    auto G4 = [&](const bf16* ah, const bf16* al, size_t off, bf16* ch, bf16* cl, int M, int N, int K) {
        bgemm<4><<<dim3(N/128, M/128), 128, DSMB>>>(ah, al, whi+off, wlo+off, nullptr, nullptr, nullptr, ch, cl, M, N, K);
    };
    auto G0 = [&](const bf16* ah, const bf16* al, size_t off, float* C, int M, int N, int K) {
        bgemm<0><<<dim3(N/128, M/128), 128, DSMB>>>(ah, al, whi+off, wlo+off, nullptr, nullptr, C, nullptr, nullptr, M, N, K);
    };

    dim3 tb(32, 8);
    wconv512_all<<<dim3(16, 16, 72), tb>>>(enc_Wq, enc_Wk, enc_Wv, enc_Wo,
                                           dec_sWq, dec_sWk, dec_sWv, dec_sWo,
                                           dec_cWq, dec_cWk, dec_cWv, dec_cWo, whi, wlo);
    embed_kernel<<<(MS*DMOD + 255)/256, 256>>>(src_ids, src_emb, x, MS);
    rmsnorm_pair_kernel<<<MS, 256>>>(x, enc_n1, hh, hl);
    G4(hh, hl, O_EQKV, qkvh, qkvl, MS, 1536, 512);            // profile window
    attn_mma<<<dim3(SSEQ/64, HHEADS, BBATCH), 256, ASMEM>>>(
        qkvh, qkvl, 1536, qkvh+512, qkvl+512, qkvh+1024, qkvl+1024, 1536,
        src_ids, rel_enc, ath, atl, SSEQ, SSEQ, 0);
    embed_kernel<<<(MT*DMOD + 255)/256, 256>>>(tgt_ids, tgt_emb, y, MT);
    wconvFF_all<<<dim3(1024, 1, 24), tb>>>(enc_W1, enc_W2, dec_W1, dec_W2, whi, wlo);
    econv_kernel<<<(VTOK*DMOD + 255)/256, 256>>>(tgt_emb, whi + O_EMB, wlo + O_EMB, VTOK*DMOD);

    for (int l = 0; l < LLAY; l++) {
        if (l > 0) {
            rmsnorm_pair_kernel<<<MS, 256>>>(x, enc_n1 + (size_t)l*DMOD, hh, hl);
            G4(hh, hl, O_EQKV + (size_t)l*3*W512, qkvh, qkvl, MS, 1536, 512);
            attn_mma<<<dim3(SSEQ/64, HHEADS, BBATCH), 256, ASMEM>>>(
                qkvh, qkvl, 1536, qkvh+512, qkvl+512, qkvh+1024, qkvl+1024, 1536,
                src_ids, rel_enc, ath, atl, SSEQ, SSEQ, 0);
        }
        G1(ath, atl, O_EWO + (size_t)l*W512, x, x, MS, 512, 512);
        rmsnorm_pair_kernel<<<MS, 256>>>(x, enc_n2 + (size_t)l*DMOD, hh, hl);
        G2(hh, hl, O_EW1 + (size_t)l*WFF, enc_b1 + (size_t)l*DFFN, fh, fl, MS, 2048, 512);
        G3(fh, fl, O_EW2 + (size_t)l*WFF, enc_b2 + (size_t)l*DMOD, x, x, MS, 512, 2048);
    }
    econv_kernel<<<(MS*DMOD + 255)/256, 256>>>(x, xh, xl, MS*DMOD);

    for (int l = 0; l < LLAY; l++) {
        rmsnorm_pair_kernel<<<MT, 256>>>(y, dec_n1 + (size_t)l*DMOD, hh, hl);
        G4(hh, hl, O_DSQKV + (size_t)l*3*W512, qkvh, qkvl, MT, 1536, 512);
        attn_mma<<<dim3(TSEQ/64, HHEADS, BBATCH), 256, ASMEM>>>(
            qkvh, qkvl, 1536, qkvh+512, qkvl+512, qkvh+1024, qkvl+1024, 1536,
            tgt_ids, rel_dec, ath, atl, TSEQ, TSEQ, 1);
        G1(ath, atl, O_DSO + (size_t)l*W512, y, y, MT, 512, 512);

        rmsnorm_pair_kernel<<<MT, 256>>>(y, dec_n2 + (size_t)l*DMOD, hh, hl);
        G4(hh, hl, O_DCQ + (size_t)l*W512, cqh, cql, MT, 512, 512);
        G4(xh, xl, O_DCKV + (size_t)l*2*W512, ckvh, ckvl, MS, 1024, 512);
        attn_mma<<<dim3(TSEQ/64, HHEADS, BBATCH), 256, ASMEM>>>(
            cqh, cql, 512, ckvh, ckvl, ckvh+512, ckvl+512, 1024,
            src_ids, nullptr, ath, atl, TSEQ, SSEQ, 0);
        G1(ath, atl, O_DCO + (size_t)l*W512, y, y, MT, 512, 512);

        rmsnorm_pair_kernel<<<MT, 256>>>(y, dec_n3 + (size_t)l*DMOD, hh, hl);
        G2(hh, hl, O_DW1 + (size_t)l*WFF, dec_b1 + (size_t)l*DFFN, fh, fl, MT, 2048, 512);
        G3(fh, fl, O_DW2 + (size_t)l*WFF, dec_b2 + (size_t)l*DMOD, y, y, MT, 512, 2048);
    }

    rmsnorm_pair_kernel<<<MT, 256>>>(y, final_w, hh, hl);
    G0(hh, hl, O_EMB, out, MT, VTOK, 512);
}